// round 1
// baseline (speedup 1.0000x reference)
#include <cuda_runtime.h>
#include <cuda_bf16.h>
#include <math.h>

// Problem constants
#define BB   1024
#define SS   49
#define DD   128
#define HH   4
#define VV   100001
#define BS   (BB*SS)      // 50176
#define NEGV (-1e8f)

typedef unsigned long long ull;

// ---------------- packed f32x2 helpers (sm_100+) ----------------
__device__ __forceinline__ ull pack2(float lo, float hi) {
    ull r; asm("mov.b64 %0, {%1, %2};" : "=l"(r) : "f"(lo), "f"(hi)); return r;
}
__device__ __forceinline__ void unpack2(ull v, float& lo, float& hi) {
    asm("mov.b64 {%0, %1}, %2;" : "=f"(lo), "=f"(hi) : "l"(v));
}
__device__ __forceinline__ ull ffma2(ull a, ull b, ull c) {
    ull d; asm("fma.rn.f32x2 %0, %1, %2, %3;" : "=l"(d) : "l"(a), "l"(b), "l"(c)); return d;
}

// ---------------- scratch (device globals: no allocs allowed) ----------------
__device__ float g_x   [BS * DD];        // embedded input
__device__ float g_qkv [BS * 3 * DD];    // q|k|v concat, ld=384
__device__ float g_av  [BS * DD];        // attention output (B,S,D)
__device__ float g_enc [BS * DD];        // encoder output
__device__ float g_pool[BB * DD];        // pooled rep

// ---------------- K1: embedding + subgenre + positional encoding ----------------
__global__ void embed_kernel(const int* __restrict__ seq, const int* __restrict__ sub,
                             const float* __restrict__ emb, const float* __restrict__ sgt,
                             float* __restrict__ x)
{
    int bs = blockIdx.x;            // 0..BS-1
    int d  = threadIdx.x;           // 0..127
    int s  = bs % SS;
    int item = seq[bs];
    int st   = sub[bs];
    float pe = (d & 1) ? cosf((float)s) : sinf((float)s);
    x[(size_t)bs * DD + d] = emb[(size_t)item * DD + d] + sgt[(size_t)st * DD + d] + pe;
}

// ---------------- shared GEMM: C[M,N] = A[M,128] @ W[128,N] + bias ----------------
// Tile 64(M) x 128(N), K=128 fully resident in smem.
// Each of 256 threads computes 4 rows x 4 f32x2 pairs (8 cols) via fma.rn.f32x2.
__global__ __launch_bounds__(256, 2)
void gemm_bias_kernel(const float* __restrict__ A, int lda,
                      const float* __restrict__ W, int ldw,
                      const float* __restrict__ bias,
                      float* __restrict__ C, int ldc,
                      int M, int N)
{
    extern __shared__ float smem[];
    float* sA = smem;               // [64][128]   32 KB
    float* sW = smem + 64 * 128;    // [128][128]  64 KB

    const int tid = threadIdx.x;
    const int n0 = blockIdx.x * 128;
    const int m0 = blockIdx.y * 64;

    // --- load A tile (vectorized; lda is always a multiple of 4 here) ---
    #pragma unroll
    for (int t = tid; t < 2048; t += 256) {
        int row = t >> 5;
        int c4  = (t & 31) << 2;
        int m = m0 + row;
        float4 v = make_float4(0.f, 0.f, 0.f, 0.f);
        if (m < M) v = *reinterpret_cast<const float4*>(A + (size_t)m * lda + c4);
        *reinterpret_cast<float4*>(sA + row * 128 + c4) = v;
    }
    // --- load W tile ---
    if ((n0 + 128 <= N) && ((ldw & 3) == 0)) {
        #pragma unroll
        for (int t = tid; t < 4096; t += 256) {
            int k  = t >> 5;
            int c4 = (t & 31) << 2;
            *reinterpret_cast<float4*>(sW + k * 128 + c4) =
                *reinterpret_cast<const float4*>(W + (size_t)k * ldw + n0 + c4);
        }
    } else {
        // scalar path (odd ldw = w_score, or ragged N edge)
        #pragma unroll 4
        for (int t = tid; t < 16384; t += 256) {
            int k = t >> 7;
            int c = t & 127;
            sW[k * 128 + c] = (n0 + c < N) ? W[(size_t)k * ldw + n0 + c] : 0.f;
        }
    }
    __syncthreads();

    const int tx = tid & 15;        // 16 col-groups (8 cols each)
    const int ty = tid >> 4;        // 16 row-groups (4 rows each)
    const float* pa = sA + (ty << 2) * 128;
    const float* pw = sW + (tx << 3);

    ull acc[4][4];
    #pragma unroll
    for (int i = 0; i < 4; i++)
        #pragma unroll
        for (int j = 0; j < 4; j++) acc[i][j] = 0ull;

    #pragma unroll 4
    for (int k = 0; k < 128; k++) {
        float a0 = pa[k];
        float a1 = pa[128 + k];
        float a2 = pa[256 + k];
        float a3 = pa[384 + k];
        ull A0 = pack2(a0, a0), A1 = pack2(a1, a1);
        ull A2 = pack2(a2, a2), A3 = pack2(a3, a3);
        const ulonglong2* wp = reinterpret_cast<const ulonglong2*>(pw + k * 128);
        ulonglong2 w01 = wp[0];   // cols (0,1),(2,3)
        ulonglong2 w23 = wp[1];   // cols (4,5),(6,7)
        acc[0][0] = ffma2(A0, w01.x, acc[0][0]); acc[0][1] = ffma2(A0, w01.y, acc[0][1]);
        acc[0][2] = ffma2(A0, w23.x, acc[0][2]); acc[0][3] = ffma2(A0, w23.y, acc[0][3]);
        acc[1][0] = ffma2(A1, w01.x, acc[1][0]); acc[1][1] = ffma2(A1, w01.y, acc[1][1]);
        acc[1][2] = ffma2(A1, w23.x, acc[1][2]); acc[1][3] = ffma2(A1, w23.y, acc[1][3]);
        acc[2][0] = ffma2(A2, w01.x, acc[2][0]); acc[2][1] = ffma2(A2, w01.y, acc[2][1]);
        acc[2][2] = ffma2(A2, w23.x, acc[2][2]); acc[2][3] = ffma2(A2, w23.y, acc[2][3]);
        acc[3][0] = ffma2(A3, w01.x, acc[3][0]); acc[3][1] = ffma2(A3, w01.y, acc[3][1]);
        acc[3][2] = ffma2(A3, w23.x, acc[3][2]); acc[3][3] = ffma2(A3, w23.y, acc[3][3]);
    }

    // --- epilogue: add bias, guarded scalar stores (ldc may be odd) ---
    #pragma unroll
    for (int i = 0; i < 4; i++) {
        int m = m0 + (ty << 2) + i;
        if (m >= M) continue;
        float* crow = C + (size_t)m * ldc;
        #pragma unroll
        for (int j = 0; j < 4; j++) {
            int n = n0 + (tx << 3) + (j << 1);
            float lo, hi; unpack2(acc[i][j], lo, hi);
            if (n     < N) crow[n]     = lo + bias[n];
            if (n + 1 < N) crow[n + 1] = hi + bias[n + 1];
        }
    }
}

// ---------------- K3: attention, one block per (b,h) ----------------
__global__ __launch_bounds__(256)
void attn_kernel(const float* __restrict__ qkv, const int* __restrict__ seq,
                 float* __restrict__ av)
{
    __shared__ float sq[SS][33], sk[SS][33], sv[SS][33];
    __shared__ float sc[SS][52];
    __shared__ int   spad[SS];

    int b = blockIdx.x >> 2;
    int h = blockIdx.x & 3;
    int tid = threadIdx.x;

    for (int idx = tid; idx < SS * 32; idx += 256) {
        int s = idx >> 5, i = idx & 31;
        size_t base = ((size_t)(b * SS + s)) * 384 + h * 32 + i;
        sq[s][i] = qkv[base];
        sk[s][i] = qkv[base + 128];
        sv[s][i] = qkv[base + 256];
    }
    if (tid < SS) spad[tid] = (seq[b * SS + tid] == 0);
    __syncthreads();

    // scores (scaled by 1/head_dim), masked
    for (int idx = tid; idx < SS * SS; idx += 256) {
        int qi = idx / SS;
        int kj = idx - qi * SS;
        float acc = 0.f;
        #pragma unroll
        for (int i = 0; i < 32; i++) acc += sq[qi][i] * sk[kj][i];
        acc *= (1.0f / 32.0f);
        if (spad[qi] | spad[kj]) acc = NEGV;
        sc[qi][kj] = acc;
    }
    __syncthreads();

    // row softmax: one warp per row, round-robin
    int wid = tid >> 5, lane = tid & 31;
    for (int r = wid; r < SS; r += 8) {
        float m = -INFINITY;
        for (int j = lane; j < SS; j += 32) m = fmaxf(m, sc[r][j]);
        #pragma unroll
        for (int o = 16; o; o >>= 1) m = fmaxf(m, __shfl_xor_sync(0xffffffffu, m, o));
        float sum = 0.f;
        for (int j = lane; j < SS; j += 32) {
            float e = expf(sc[r][j] - m);
            sc[r][j] = e;
            sum += e;
        }
        #pragma unroll
        for (int o = 16; o; o >>= 1) sum += __shfl_xor_sync(0xffffffffu, sum, o);
        float inv = 1.0f / sum;
        for (int j = lane; j < SS; j += 32) sc[r][j] *= inv;
    }
    __syncthreads();

    // attn @ v  -> write back in [B,S,D] layout (transposed merge of heads)
    for (int idx = tid; idx < SS * 32; idx += 256) {
        int s = idx >> 5, i = idx & 31;
        float acc = 0.f;
        #pragma unroll
        for (int j = 0; j < SS; j++) acc += sc[s][j] * sv[j][i];
        av[((size_t)(b * SS + s)) * DD + h * 32 + i] = acc;
    }
}

// ---------------- K5: SelfEnc pooling, one block per batch ----------------
__global__ __launch_bounds__(128)
void pool_kernel(const float* __restrict__ enc, const float* __restrict__ w_enc,
                 const float* __restrict__ b_enc, float* __restrict__ pooled)
{
    __shared__ float se[SS][DD];
    __shared__ float swt[SS];
    __shared__ float swe[DD];
    int b = blockIdx.x;
    int tid = threadIdx.x;      // 128

    swe[tid] = w_enc[tid];
    for (int idx = tid; idx < SS * DD; idx += 128)
        se[idx >> 7][idx & 127] = enc[(size_t)b * SS * DD + idx];
    __syncthreads();

    int wid = tid >> 5, lane = tid & 31;
    for (int s = wid; s < SS; s += 4) {
        float acc = 0.f;
        #pragma unroll
        for (int d = lane; d < DD; d += 32) acc += se[s][d] * swe[d];
        #pragma unroll
        for (int o = 16; o; o >>= 1) acc += __shfl_xor_sync(0xffffffffu, acc, o);
        if (lane == 0) swt[s] = acc + b_enc[0];
    }
    __syncthreads();

    float acc = 0.f;
    #pragma unroll
    for (int s = 0; s < SS; s++) acc += swt[s] * se[s][tid];
    pooled[b * DD + tid] = acc;
}

// ---------------- K7: consumed-item mask scatter ----------------
__global__ void mask_kernel(const int* __restrict__ seq, float* __restrict__ out)
{
    int b = blockIdx.x;
    int s = threadIdx.x;
    if (s < SS) out[(size_t)b * VV + seq[b * SS + s]] = NEGV;
}

// ---------------- launch ----------------
extern "C" void kernel_launch(void* const* d_in, const int* in_sizes, int n_in,
                              void* d_out, int out_size)
{
    const int*   seq    = (const int*)  d_in[0];
    const int*   subty  = (const int*)  d_in[1];
    const float* emb    = (const float*)d_in[2];
    const float* sgt    = (const float*)d_in[3];
    const float* wq     = (const float*)d_in[4];
    const float* bq     = (const float*)d_in[5];
    const float* wk     = (const float*)d_in[6];
    const float* bk     = (const float*)d_in[7];
    const float* wv     = (const float*)d_in[8];
    const float* bv     = (const float*)d_in[9];
    const float* wo     = (const float*)d_in[10];
    const float* bo     = (const float*)d_in[11];
    const float* w_enc  = (const float*)d_in[12];
    const float* b_enc  = (const float*)d_in[13];
    const float* wscore = (const float*)d_in[14];
    const float* bscore = (const float*)d_in[15];
    float* out = (float*)d_out;

    float *px, *pqkv, *pav, *penc, *ppool;
    cudaGetSymbolAddress((void**)&px,    g_x);
    cudaGetSymbolAddress((void**)&pqkv,  g_qkv);
    cudaGetSymbolAddress((void**)&pav,   g_av);
    cudaGetSymbolAddress((void**)&penc,  g_enc);
    cudaGetSymbolAddress((void**)&ppool, g_pool);

    const int GEMM_SMEM = 96 * 1024;
    cudaFuncSetAttribute(gemm_bias_kernel,
                         cudaFuncAttributeMaxDynamicSharedMemorySize, GEMM_SMEM);

    // 1) embed + PE
    embed_kernel<<<BS, 128>>>(seq, subty, emb, sgt, px);

    // 2) QKV projections (3 calls into concat buffer, ld=384)
    dim3 gproj(1, BS / 64);
    gemm_bias_kernel<<<gproj, 256, GEMM_SMEM>>>(px, DD, wq, DD, bq, pqkv + 0,   384, BS, DD);
    gemm_bias_kernel<<<gproj, 256, GEMM_SMEM>>>(px, DD, wk, DD, bk, pqkv + 128, 384, BS, DD);
    gemm_bias_kernel<<<gproj, 256, GEMM_SMEM>>>(px, DD, wv, DD, bv, pqkv + 256, 384, BS, DD);

    // 3) attention
    attn_kernel<<<BB * HH, 256>>>(pqkv, seq, pav);

    // 4) output projection
    gemm_bias_kernel<<<gproj, 256, GEMM_SMEM>>>(pav, DD, wo, DD, bo, penc, DD, BS, DD);

    // 5) pooling
    pool_kernel<<<BB, 128>>>(penc, w_enc, b_enc, ppool);

    // 6) novelty scores: pooled[1024,128] @ w_score[128,100001] + b_score
    dim3 gscore((VV + 127) / 128, BB / 64);
    gemm_bias_kernel<<<gscore, 256, GEMM_SMEM>>>(ppool, DD, wscore, VV, bscore,
                                                 out, VV, BB, VV);

    // 7) consumed mask
    mask_kernel<<<BB, 64>>>(seq, out);
}

// round 3
// speedup vs baseline: 2.0645x; 2.0645x over previous
#include <cuda_runtime.h>
#include <cuda_bf16.h>
#include <math.h>
#include <stdint.h>

// Problem constants
#define BB   1024
#define SS   49
#define DD   128
#define HH   4
#define VV   100001
#define VV_PAD 100096            // 782 * 128
#define BS   (BB*SS)             // 50176
#define NEGV (-1e8f)

// =====================================================================
// scratch (device globals: no allocs allowed)
// =====================================================================
__device__ __align__(256) __nv_bfloat16 g_xhi [BS * DD];
__device__ __align__(256) __nv_bfloat16 g_xlo [BS * DD];
__device__ __align__(256) float         g_qkv [BS * 3 * DD];   // q|k|v concat, ld=384
__device__ __align__(256) float         g_av  [BS * DD];
__device__ __align__(256) __nv_bfloat16 g_avhi[BS * DD];
__device__ __align__(256) __nv_bfloat16 g_avlo[BS * DD];
__device__ __align__(256) float         g_enc [BS * DD];
__device__ __align__(256) float         g_pool[BB * DD];
__device__ __align__(256) __nv_bfloat16 g_phi [BB * DD];
__device__ __align__(256) __nv_bfloat16 g_plo [BB * DD];
__device__ __align__(256) __nv_bfloat16 g_wshi[(size_t)VV_PAD * DD];  // w_score^T hi [n][k]
__device__ __align__(256) __nv_bfloat16 g_wslo[(size_t)VV_PAD * DD];  // w_score^T lo
__device__ __align__(256) __nv_bfloat16 g_w4hi[4][DD * DD];           // wq,wk,wv,wo ^T hi
__device__ __align__(256) __nv_bfloat16 g_w4lo[4][DD * DD];

// =====================================================================
// warp MMA: m16n8k16 bf16 -> fp32 accumulate
// =====================================================================
__device__ __forceinline__ void mma_bf16(float* c, const uint32_t* a, const uint32_t* b) {
    asm volatile(
        "mma.sync.aligned.m16n8k16.row.col.f32.bf16.bf16.f32 "
        "{%0,%1,%2,%3}, {%4,%5,%6,%7}, {%8,%9}, {%0,%1,%2,%3};"
        : "+f"(c[0]), "+f"(c[1]), "+f"(c[2]), "+f"(c[3])
        : "r"(a[0]), "r"(a[1]), "r"(a[2]), "r"(a[3]), "r"(b[0]), "r"(b[1]));
}

// smem tile geometry: 128 rows x 128 bf16, padded row stride = 272 bytes
#define ROWB 272
#define TILE_SMEM (128 * ROWB)   // 34816

// =====================================================================
// K1: embedding + subgenre + positional encoding -> bf16 hi/lo
// =====================================================================
__global__ void embed_kernel(const int* __restrict__ seq, const int* __restrict__ sub,
                             const float* __restrict__ emb, const float* __restrict__ sgt,
                             __nv_bfloat16* __restrict__ xhi, __nv_bfloat16* __restrict__ xlo)
{
    int bs = blockIdx.x;
    int d  = threadIdx.x;
    int s  = bs % SS;
    int item = seq[bs];
    int st   = sub[bs];
    float pe = (d & 1) ? cosf((float)s) : sinf((float)s);
    float v  = emb[(size_t)item * DD + d] + sgt[(size_t)st * DD + d] + pe;
    __nv_bfloat16 h = __float2bfloat16(v);
    xhi[(size_t)bs * DD + d] = h;
    xlo[(size_t)bs * DD + d] = __float2bfloat16(v - __bfloat162float(h));
}

// =====================================================================
// K2: elementwise fp32 -> bf16 hi/lo split
// =====================================================================
__global__ void split_kernel(const float* __restrict__ in,
                             __nv_bfloat16* __restrict__ hi,
                             __nv_bfloat16* __restrict__ lo, int n)
{
    int i = blockIdx.x * 256 + threadIdx.x;
    if (i >= n) return;
    float v = in[i];
    __nv_bfloat16 h = __float2bfloat16(v);
    hi[i] = h;
    lo[i] = __float2bfloat16(v - __bfloat162float(h));
}

// =====================================================================
// K3: weight transpose + split:  W[k=128][n] (ldw) -> T[n][k=128] bf16 hi/lo
// =====================================================================
__global__ __launch_bounds__(128)
void wsplit_kernel(const float* __restrict__ W, int ldw, int nvalid,
                   __nv_bfloat16* __restrict__ Thi, __nv_bfloat16* __restrict__ Tlo)
{
    __shared__ float st[32][129];
    int t = threadIdx.x;
    int n0 = blockIdx.x * 32;
    #pragma unroll
    for (int rep = 0; rep < 32; rep++) {
        int i = rep * 128 + t;          // 4096 elements
        int k = i >> 5, j = i & 31;
        int n = n0 + j;
        st[j][k] = (n < nvalid) ? W[(size_t)k * ldw + n] : 0.f;
    }
    __syncthreads();
    #pragma unroll
    for (int rep = 0; rep < 32; rep++) {
        int i = rep * 128 + t;
        int nl = i >> 7, k = i & 127;
        float v = st[nl][k];
        __nv_bfloat16 h = __float2bfloat16(v);
        size_t o = (size_t)(n0 + nl) * DD + k;
        Thi[o] = h;
        Tlo[o] = __float2bfloat16(v - __bfloat162float(h));
    }
}

// =====================================================================
// K4: bf16x3 tensor-core GEMM via mma.sync
// C[m0:128, n0:128] = A[.,128] @ B^T[.,128]  (+bias)
// A,B row-major [row][k=128] bf16 (hi/lo pairs). grid=(nTiles,mBlocks).
// Each CTA: 256 threads, loops m_iters M-tiles keeping B resident.
// =====================================================================
__device__ __forceinline__ void load_tile(char* s, const __nv_bfloat16* g, int t)
{
    #pragma unroll
    for (int i = 0; i < 8; i++) {
        int idx = i * 256 + t;          // 2048 uint4
        int r = idx >> 4, seg = idx & 15;
        uint4 v = *reinterpret_cast<const uint4*>(g + (size_t)r * DD + seg * 8);
        *reinterpret_cast<uint4*>(s + r * ROWB + seg * 16) = v;
    }
}

__global__ __launch_bounds__(256, 1)
void mma_gemm(const __nv_bfloat16* __restrict__ Ahi, const __nv_bfloat16* __restrict__ Alo,
              const __nv_bfloat16* __restrict__ Bhi, const __nv_bfloat16* __restrict__ Blo,
              const float* __restrict__ bias, float* __restrict__ C,
              long long ldc, int nvalid, int m_iters)
{
    extern __shared__ char sm[];
    char* sBhi = sm;
    char* sBlo = sBhi + TILE_SMEM;
    char* sAhi = sBlo + TILE_SMEM;
    char* sAlo = sAhi + TILE_SMEM;
    float* sbias = (float*)(sAlo + TILE_SMEM);

    const int t = threadIdx.x;
    const int lane = t & 31;
    const int wid  = t >> 5;
    const int warp_m = wid >> 2;        // 0..1  (64 rows each)
    const int warp_n = wid & 3;         // 0..3  (32 cols each)
    const int n0 = blockIdx.x * 128;

    // ---- B tiles + bias: loaded once, reused across all M iterations ----
    load_tile(sBhi, Bhi + (size_t)n0 * DD, t);
    load_tile(sBlo, Blo + (size_t)n0 * DD, t);
    if (t < 128) {
        int n = n0 + t;
        sbias[t] = (n < nvalid) ? bias[n] : 0.f;
    }

    const int frow = lane >> 2;         // 0..7
    const int fcol = (lane & 3) * 4;    // byte offset of 2-bf16 pair

    for (int iter = 0; iter < m_iters; iter++) {
        const int m0 = (blockIdx.y * m_iters + iter) * 128;
        __syncthreads();                // previous compute done before overwrite
        load_tile(sAhi, Ahi + (size_t)m0 * DD, t);
        load_tile(sAlo, Alo + (size_t)m0 * DD, t);
        __syncthreads();

        float acc[4][4][4];
        #pragma unroll
        for (int mi = 0; mi < 4; mi++)
            #pragma unroll
            for (int ni = 0; ni < 4; ni++)
                #pragma unroll
                for (int e = 0; e < 4; e++) acc[mi][ni][e] = 0.f;

        #pragma unroll
        for (int kb = 0; kb < 8; kb++) {
            const int koff = kb * 32 + fcol;   // byte offset of this lane's k-pair

            uint32_t bh[4][2], bl[4][2];
            #pragma unroll
            for (int ni = 0; ni < 4; ni++) {
                const char* bb = sBhi + (warp_n * 32 + ni * 8 + frow) * ROWB + koff;
                bh[ni][0] = *(const uint32_t*)(bb);
                bh[ni][1] = *(const uint32_t*)(bb + 16);
                const char* bb2 = sBlo + (warp_n * 32 + ni * 8 + frow) * ROWB + koff;
                bl[ni][0] = *(const uint32_t*)(bb2);
                bl[ni][1] = *(const uint32_t*)(bb2 + 16);
            }
            uint32_t a[4][4];
            #pragma unroll
            for (int mi = 0; mi < 4; mi++) {
                const char* ab = sAhi + (warp_m * 64 + mi * 16 + frow) * ROWB + koff;
                a[mi][0] = *(const uint32_t*)(ab);
                a[mi][1] = *(const uint32_t*)(ab + 8 * ROWB);
                a[mi][2] = *(const uint32_t*)(ab + 16);
                a[mi][3] = *(const uint32_t*)(ab + 8 * ROWB + 16);
            }
            #pragma unroll
            for (int mi = 0; mi < 4; mi++)
                #pragma unroll
                for (int ni = 0; ni < 4; ni++) {
                    mma_bf16(acc[mi][ni], a[mi], bh[ni]);   // Ah*Bh
                    mma_bf16(acc[mi][ni], a[mi], bl[ni]);   // Ah*Bl
                }
            #pragma unroll
            for (int mi = 0; mi < 4; mi++) {
                const char* ab = sAlo + (warp_m * 64 + mi * 16 + frow) * ROWB + koff;
                a[mi][0] = *(const uint32_t*)(ab);
                a[mi][1] = *(const uint32_t*)(ab + 8 * ROWB);
                a[mi][2] = *(const uint32_t*)(ab + 16);
                a[mi][3] = *(const uint32_t*)(ab + 8 * ROWB + 16);
            }
            #pragma unroll
            for (int mi = 0; mi < 4; mi++)
                #pragma unroll
                for (int ni = 0; ni < 4; ni++)
                    mma_bf16(acc[mi][ni], a[mi], bh[ni]);   // Al*Bh
        }

        // ---- epilogue ----
        #pragma unroll
        for (int mi = 0; mi < 4; mi++) {
            const int r0 = m0 + warp_m * 64 + mi * 16 + frow;
            float* crow0 = C + (long long)r0 * ldc;
            float* crow1 = C + (long long)(r0 + 8) * ldc;
            #pragma unroll
            for (int ni = 0; ni < 4; ni++) {
                const int nl = warp_n * 32 + ni * 8 + (lane & 3) * 2;  // local col
                const int n  = n0 + nl;
                const float b0 = sbias[nl], b1 = sbias[nl + 1];
                if (n < nvalid) {
                    crow0[n] = acc[mi][ni][0] + b0;
                    crow1[n] = acc[mi][ni][2] + b0;
                }
                if (n + 1 < nvalid) {
                    crow0[n + 1] = acc[mi][ni][1] + b1;
                    crow1[n + 1] = acc[mi][ni][3] + b1;
                }
            }
        }
    }
}

// =====================================================================
// K5: attention, one block per (b,h)
// =====================================================================
__global__ __launch_bounds__(256)
void attn_kernel(const float* __restrict__ qkv, const int* __restrict__ seq,
                 float* __restrict__ av)
{
    __shared__ float sq[SS][33], sk[SS][33], sv[SS][33];
    __shared__ float sc[SS][52];
    __shared__ int   spad[SS];

    int b = blockIdx.x >> 2;
    int h = blockIdx.x & 3;
    int tid = threadIdx.x;

    for (int idx = tid; idx < SS * 32; idx += 256) {
        int s = idx >> 5, i = idx & 31;
        size_t base = ((size_t)(b * SS + s)) * 384 + h * 32 + i;
        sq[s][i] = qkv[base];
        sk[s][i] = qkv[base + 128];
        sv[s][i] = qkv[base + 256];
    }
    if (tid < SS) spad[tid] = (seq[b * SS + tid] == 0);
    __syncthreads();

    for (int idx = tid; idx < SS * SS; idx += 256) {
        int qi = idx / SS;
        int kj = idx - qi * SS;
        float acc = 0.f;
        #pragma unroll
        for (int i = 0; i < 32; i++) acc += sq[qi][i] * sk[kj][i];
        acc *= (1.0f / 32.0f);
        if (spad[qi] | spad[kj]) acc = NEGV;
        sc[qi][kj] = acc;
    }
    __syncthreads();

    int wid = tid >> 5, lane = tid & 31;
    for (int r = wid; r < SS; r += 8) {
        float m = -INFINITY;
        for (int j = lane; j < SS; j += 32) m = fmaxf(m, sc[r][j]);
        #pragma unroll
        for (int o = 16; o; o >>= 1) m = fmaxf(m, __shfl_xor_sync(0xffffffffu, m, o));
        float sum = 0.f;
        for (int j = lane; j < SS; j += 32) {
            float e = expf(sc[r][j] - m);
            sc[r][j] = e;
            sum += e;
        }
        #pragma unroll
        for (int o = 16; o; o >>= 1) sum += __shfl_xor_sync(0xffffffffu, sum, o);
        float inv = 1.0f / sum;
        for (int j = lane; j < SS; j += 32) sc[r][j] *= inv;
    }
    __syncthreads();

    for (int idx = tid; idx < SS * 32; idx += 256) {
        int s = idx >> 5, i = idx & 31;
        float acc = 0.f;
        #pragma unroll
        for (int j = 0; j < SS; j++) acc += sc[s][j] * sv[j][i];
        av[((size_t)(b * SS + s)) * DD + h * 32 + i] = acc;
    }
}

// =====================================================================
// K6: SelfEnc pooling, one block per batch
// =====================================================================
__global__ __launch_bounds__(128)
void pool_kernel(const float* __restrict__ enc, const float* __restrict__ w_enc,
                 const float* __restrict__ b_enc, float* __restrict__ pooled)
{
    __shared__ float se[SS][DD];
    __shared__ float swt[SS];
    __shared__ float swe[DD];
    int b = blockIdx.x;
    int tid = threadIdx.x;

    swe[tid] = w_enc[tid];
    for (int idx = tid; idx < SS * DD; idx += 128)
        se[idx >> 7][idx & 127] = enc[(size_t)b * SS * DD + idx];
    __syncthreads();

    int wid = tid >> 5, lane = tid & 31;
    for (int s = wid; s < SS; s += 4) {
        float acc = 0.f;
        #pragma unroll
        for (int d = lane; d < DD; d += 32) acc += se[s][d] * swe[d];
        #pragma unroll
        for (int o = 16; o; o >>= 1) acc += __shfl_xor_sync(0xffffffffu, acc, o);
        if (lane == 0) swt[s] = acc + b_enc[0];
    }
    __syncthreads();

    float acc = 0.f;
    #pragma unroll
    for (int s = 0; s < SS; s++) acc += swt[s] * se[s][tid];
    pooled[b * DD + tid] = acc;
}

// =====================================================================
// K7: consumed-item mask scatter
// =====================================================================
__global__ void mask_kernel(const int* __restrict__ seq, float* __restrict__ out)
{
    int b = blockIdx.x;
    int s = threadIdx.x;
    if (s < SS) out[(size_t)b * VV + seq[b * SS + s]] = NEGV;
}

// =====================================================================
// launch
// =====================================================================
extern "C" void kernel_launch(void* const* d_in, const int* in_sizes, int n_in,
                              void* d_out, int out_size)
{
    const int*   seq    = (const int*)  d_in[0];
    const int*   subty  = (const int*)  d_in[1];
    const float* emb    = (const float*)d_in[2];
    const float* sgt    = (const float*)d_in[3];
    const float* wq     = (const float*)d_in[4];
    const float* bq     = (const float*)d_in[5];
    const float* wk     = (const float*)d_in[6];
    const float* bk     = (const float*)d_in[7];
    const float* wv     = (const float*)d_in[8];
    const float* bv     = (const float*)d_in[9];
    const float* wo     = (const float*)d_in[10];
    const float* bo     = (const float*)d_in[11];
    const float* w_enc  = (const float*)d_in[12];
    const float* b_enc  = (const float*)d_in[13];
    const float* wscore = (const float*)d_in[14];
    const float* bscore = (const float*)d_in[15];
    float* out = (float*)d_out;

    __nv_bfloat16 *xhi, *xlo, *avhi, *avlo, *phi, *plo, *wshi, *wslo, *w4hi, *w4lo;
    float *qkv, *av, *enc, *pool;
    cudaGetSymbolAddress((void**)&xhi,  g_xhi);
    cudaGetSymbolAddress((void**)&xlo,  g_xlo);
    cudaGetSymbolAddress((void**)&qkv,  g_qkv);
    cudaGetSymbolAddress((void**)&av,   g_av);
    cudaGetSymbolAddress((void**)&avhi, g_avhi);
    cudaGetSymbolAddress((void**)&avlo, g_avlo);
    cudaGetSymbolAddress((void**)&enc,  g_enc);
    cudaGetSymbolAddress((void**)&pool, g_pool);
    cudaGetSymbolAddress((void**)&phi,  g_phi);
    cudaGetSymbolAddress((void**)&plo,  g_plo);
    cudaGetSymbolAddress((void**)&wshi, g_wshi);
    cudaGetSymbolAddress((void**)&wslo, g_wslo);
    cudaGetSymbolAddress((void**)&w4hi, g_w4hi);
    cudaGetSymbolAddress((void**)&w4lo, g_w4lo);

    const int GEMM_SMEM = 4 * TILE_SMEM + 512;   // 139776
    cudaFuncSetAttribute(mma_gemm, cudaFuncAttributeMaxDynamicSharedMemorySize, GEMM_SMEM);

    // 1) embed + PE -> bf16 hi/lo
    embed_kernel<<<BS, 128>>>(seq, subty, emb, sgt, xhi, xlo);

    // 2) weight transpose + split
    wsplit_kernel<<<4, 128>>>(wq, DD, DD, w4hi + 0 * DD * DD, w4lo + 0 * DD * DD);
    wsplit_kernel<<<4, 128>>>(wk, DD, DD, w4hi + 1 * DD * DD, w4lo + 1 * DD * DD);
    wsplit_kernel<<<4, 128>>>(wv, DD, DD, w4hi + 2 * DD * DD, w4lo + 2 * DD * DD);
    wsplit_kernel<<<4, 128>>>(wo, DD, DD, w4hi + 3 * DD * DD, w4lo + 3 * DD * DD);
    wsplit_kernel<<<VV_PAD / 32, 128>>>(wscore, VV, VV, wshi, wslo);

    // 3) QKV projections (tensor core): C into qkv concat (ldc=384)
    dim3 gproj(1, BS / 128);   // (1, 392)
    mma_gemm<<<gproj, 256, GEMM_SMEM>>>(xhi, xlo, w4hi + 0 * DD * DD, w4lo + 0 * DD * DD,
                                        bq, qkv + 0,   384, DD, 1);
    mma_gemm<<<gproj, 256, GEMM_SMEM>>>(xhi, xlo, w4hi + 1 * DD * DD, w4lo + 1 * DD * DD,
                                        bk, qkv + 128, 384, DD, 1);
    mma_gemm<<<gproj, 256, GEMM_SMEM>>>(xhi, xlo, w4hi + 2 * DD * DD, w4lo + 2 * DD * DD,
                                        bv, qkv + 256, 384, DD, 1);

    // 4) attention
    attn_kernel<<<BB * HH, 256>>>(qkv, seq, av);

    // 5) output projection
    split_kernel<<<(BS * DD + 255) / 256, 256>>>(av, avhi, avlo, BS * DD);
    mma_gemm<<<gproj, 256, GEMM_SMEM>>>(avhi, avlo, w4hi + 3 * DD * DD, w4lo + 3 * DD * DD,
                                        bo, enc, DD, DD, 1);

    // 6) pooling
    pool_kernel<<<BB, 128>>>(enc, w_enc, b_enc, pool);
    split_kernel<<<(BB * DD + 255) / 256, 256>>>(pool, phi, plo, BB * DD);

    // 7) novelty scores: B resident, loop all 8 M-tiles per CTA
    dim3 gscore(VV_PAD / 128, 1);   // (782, 1)
    mma_gemm<<<gscore, 256, GEMM_SMEM>>>(phi, plo, wshi, wslo, bscore, out,
                                         (long long)VV, VV, BB / 128);

    // 8) consumed mask
    mask_kernel<<<BB, 64>>>(seq, out);
}

// round 4
// speedup vs baseline: 2.2792x; 1.1040x over previous
#include <cuda_runtime.h>
#include <cuda_bf16.h>
#include <math.h>
#include <stdint.h>

// Problem constants
#define BB   1024
#define SS   49
#define DD   128
#define HH   4
#define VV   100001
#define VV_PAD 100096            // 782 * 128
#define BS   (BB*SS)             // 50176
#define NEGV (-1e8f)

// =====================================================================
// scratch (device globals: no allocs allowed)
// =====================================================================
__device__ __align__(256) __nv_bfloat16 g_xhi [BS * DD];
__device__ __align__(256) __nv_bfloat16 g_xlo [BS * DD];
__device__ __align__(256) float         g_qkv [BS * 3 * DD];   // q|k|v concat, ld=384
__device__ __align__(256) __nv_bfloat16 g_avhi[BS * DD];
__device__ __align__(256) __nv_bfloat16 g_avlo[BS * DD];
__device__ __align__(256) float         g_enc [BS * DD];
__device__ __align__(256) __nv_bfloat16 g_phi [BB * DD];
__device__ __align__(256) __nv_bfloat16 g_plo [BB * DD];
__device__ __align__(256) __nv_bfloat16 g_wshi[(size_t)VV_PAD * DD];  // w_score^T hi [n][k]
__device__ __align__(256) __nv_bfloat16 g_wslo[(size_t)VV_PAD * DD];  // w_score^T lo
__device__ __align__(256) __nv_bfloat16 g_w4hi[4][DD * DD];           // wq,wk,wv,wo ^T hi
__device__ __align__(256) __nv_bfloat16 g_w4lo[4][DD * DD];
__device__ __align__(256) float         g_b3  [3 * DD];               // bq|bk|bv concat

// =====================================================================
// warp MMA: m16n8k16 bf16 -> fp32 accumulate
// =====================================================================
__device__ __forceinline__ void mma_bf16(float* c, const uint32_t* a, const uint32_t* b) {
    asm volatile(
        "mma.sync.aligned.m16n8k16.row.col.f32.bf16.bf16.f32 "
        "{%0,%1,%2,%3}, {%4,%5,%6,%7}, {%8,%9}, {%0,%1,%2,%3};"
        : "+f"(c[0]), "+f"(c[1]), "+f"(c[2]), "+f"(c[3])
        : "r"(a[0]), "r"(a[1]), "r"(a[2]), "r"(a[3]), "r"(b[0]), "r"(b[1]));
}

// smem tile geometry: rows x 128 bf16, padded row stride = 272 bytes
// (272 = 68 words; 68*r mod 32 = 4r mod 32 -> 8 fragment rows hit 8 distinct
//  bank groups -> conflict-free 32-bit fragment loads)
#define ROWB 272
#define TILE_B_SMEM (128 * ROWB)   // 34816
#define TILE_A_SMEM (64  * ROWB)   // 17408

// =====================================================================
// K1: embedding + subgenre + positional encoding -> bf16 hi/lo
// =====================================================================
__global__ void embed_kernel(const int* __restrict__ seq, const int* __restrict__ sub,
                             const float* __restrict__ emb, const float* __restrict__ sgt,
                             __nv_bfloat16* __restrict__ xhi, __nv_bfloat16* __restrict__ xlo)
{
    int bs = blockIdx.x;
    int d  = threadIdx.x;
    int s  = bs % SS;
    int item = seq[bs];
    int st   = sub[bs];
    float pe = (d & 1) ? cosf((float)s) : sinf((float)s);
    float v  = emb[(size_t)item * DD + d] + sgt[(size_t)st * DD + d] + pe;
    __nv_bfloat16 h = __float2bfloat16(v);
    xhi[(size_t)bs * DD + d] = h;
    xlo[(size_t)bs * DD + d] = __float2bfloat16(v - __bfloat162float(h));
}

// =====================================================================
// K2: fused transpose+split for the four 128x128 weights
// grid = (4 n-blocks, 4 weights)
// =====================================================================
__global__ __launch_bounds__(128)
void wsplit4_kernel(const float* __restrict__ w0, const float* __restrict__ w1,
                    const float* __restrict__ w2, const float* __restrict__ w3,
                    __nv_bfloat16* __restrict__ Thi4, __nv_bfloat16* __restrict__ Tlo4)
{
    __shared__ float st[32][129];
    int t = threadIdx.x;
    int n0 = blockIdx.x * 32;
    int w  = blockIdx.y;
    const float* W = (w == 0) ? w0 : (w == 1) ? w1 : (w == 2) ? w2 : w3;
    __nv_bfloat16* Thi = Thi4 + (size_t)w * DD * DD;
    __nv_bfloat16* Tlo = Tlo4 + (size_t)w * DD * DD;
    #pragma unroll
    for (int rep = 0; rep < 32; rep++) {
        int i = rep * 128 + t;
        int k = i >> 5, j = i & 31;
        st[j][k] = W[(size_t)k * DD + n0 + j];
    }
    __syncthreads();
    #pragma unroll
    for (int rep = 0; rep < 32; rep++) {
        int i = rep * 128 + t;
        int nl = i >> 7, k = i & 127;
        float v = st[nl][k];
        __nv_bfloat16 h = __float2bfloat16(v);
        size_t o = (size_t)(n0 + nl) * DD + k;
        Thi[o] = h;
        Tlo[o] = __float2bfloat16(v - __bfloat162float(h));
    }
}

// =====================================================================
// K3: transpose+split for w_score: W[k=128][VV] -> T[VV_PAD][128] hi/lo
// =====================================================================
__global__ __launch_bounds__(128)
void wsplitV_kernel(const float* __restrict__ W,
                    __nv_bfloat16* __restrict__ Thi, __nv_bfloat16* __restrict__ Tlo)
{
    __shared__ float st[32][129];
    int t = threadIdx.x;
    int n0 = blockIdx.x * 32;
    #pragma unroll
    for (int rep = 0; rep < 32; rep++) {
        int i = rep * 128 + t;
        int k = i >> 5, j = i & 31;
        int n = n0 + j;
        st[j][k] = (n < VV) ? W[(size_t)k * VV + n] : 0.f;
    }
    __syncthreads();
    #pragma unroll
    for (int rep = 0; rep < 32; rep++) {
        int i = rep * 128 + t;
        int nl = i >> 7, k = i & 127;
        float v = st[nl][k];
        __nv_bfloat16 h = __float2bfloat16(v);
        size_t o = (size_t)(n0 + nl) * DD + k;
        Thi[o] = h;
        Tlo[o] = __float2bfloat16(v - __bfloat162float(h));
    }
}

// =====================================================================
// K4: bias concat bq|bk|bv
// =====================================================================
__global__ void bias3_kernel(const float* __restrict__ bq, const float* __restrict__ bk,
                             const float* __restrict__ bv, float* __restrict__ b3)
{
    int t = threadIdx.x;   // 384
    b3[t] = (t < 128) ? bq[t] : (t < 256) ? bk[t - 128] : bv[t - 256];
}

// =====================================================================
// K5: bf16x3 tensor-core GEMM via mma.sync  (M-tile 64, N-tile 128)
// C[m,n] = A[m,k=128] @ B[n,k=128]^T + bias[n]
// grid=(nTiles, mGroups); each CTA loops m_iters M-tiles with B resident.
// smem 105KB -> 2 CTAs/SM.
// =====================================================================
__device__ __forceinline__ void load_tile_128(char* s, const __nv_bfloat16* g, int t)
{
    #pragma unroll
    for (int i = 0; i < 8; i++) {
        int idx = i * 256 + t;          // 2048 uint4
        int r = idx >> 4, seg = idx & 15;
        uint4 v = *reinterpret_cast<const uint4*>(g + (size_t)r * DD + seg * 8);
        *reinterpret_cast<uint4*>(s + r * ROWB + seg * 16) = v;
    }
}
__device__ __forceinline__ void load_tile_64(char* s, const __nv_bfloat16* g, int t)
{
    #pragma unroll
    for (int i = 0; i < 4; i++) {
        int idx = i * 256 + t;          // 1024 uint4
        int r = idx >> 4, seg = idx & 15;
        uint4 v = *reinterpret_cast<const uint4*>(g + (size_t)r * DD + seg * 8);
        *reinterpret_cast<uint4*>(s + r * ROWB + seg * 16) = v;
    }
}

__global__ __launch_bounds__(256, 2)
void mma_gemm(const __nv_bfloat16* __restrict__ Ahi, const __nv_bfloat16* __restrict__ Alo,
              const __nv_bfloat16* __restrict__ Bhi, const __nv_bfloat16* __restrict__ Blo,
              const float* __restrict__ bias, float* __restrict__ C,
              long long ldc, int nvalid, int m_iters)
{
    extern __shared__ char sm[];
    char* sBhi = sm;
    char* sBlo = sBhi + TILE_B_SMEM;
    char* sAhi = sBlo + TILE_B_SMEM;
    char* sAlo = sAhi + TILE_A_SMEM;
    float* sbias = (float*)(sAlo + TILE_A_SMEM);

    const int t = threadIdx.x;
    const int lane = t & 31;
    const int wid  = t >> 5;
    const int warp_m = wid >> 2;        // 0..1  (32 rows each)
    const int warp_n = wid & 3;         // 0..3  (32 cols each)
    const int n0 = blockIdx.x * 128;

    // ---- B tiles + bias: loaded once, reused across all M iterations ----
    load_tile_128(sBhi, Bhi + (size_t)n0 * DD, t);
    load_tile_128(sBlo, Blo + (size_t)n0 * DD, t);
    if (t < 128) {
        int n = n0 + t;
        sbias[t] = (n < nvalid) ? bias[n] : 0.f;
    }

    const int frow = lane >> 2;         // 0..7
    const int fcol = (lane & 3) * 4;    // byte offset of 2-bf16 pair

    for (int iter = 0; iter < m_iters; iter++) {
        const int m0 = (blockIdx.y * m_iters + iter) * 64;
        __syncthreads();                // previous compute done before overwrite
        load_tile_64(sAhi, Ahi + (size_t)m0 * DD, t);
        load_tile_64(sAlo, Alo + (size_t)m0 * DD, t);
        __syncthreads();

        float acc[2][4][4];
        #pragma unroll
        for (int mi = 0; mi < 2; mi++)
            #pragma unroll
            for (int ni = 0; ni < 4; ni++)
                #pragma unroll
                for (int e = 0; e < 4; e++) acc[mi][ni][e] = 0.f;

        #pragma unroll
        for (int kb = 0; kb < 8; kb++) {
            const int koff = kb * 32 + fcol;

            uint32_t bh[4][2], bl[4][2];
            #pragma unroll
            for (int ni = 0; ni < 4; ni++) {
                const char* bb = sBhi + (warp_n * 32 + ni * 8 + frow) * ROWB + koff;
                bh[ni][0] = *(const uint32_t*)(bb);
                bh[ni][1] = *(const uint32_t*)(bb + 16);
                const char* bb2 = sBlo + (warp_n * 32 + ni * 8 + frow) * ROWB + koff;
                bl[ni][0] = *(const uint32_t*)(bb2);
                bl[ni][1] = *(const uint32_t*)(bb2 + 16);
            }
            uint32_t a[2][4];
            #pragma unroll
            for (int mi = 0; mi < 2; mi++) {
                const char* ab = sAhi + (warp_m * 32 + mi * 16 + frow) * ROWB + koff;
                a[mi][0] = *(const uint32_t*)(ab);
                a[mi][1] = *(const uint32_t*)(ab + 8 * ROWB);
                a[mi][2] = *(const uint32_t*)(ab + 16);
                a[mi][3] = *(const uint32_t*)(ab + 8 * ROWB + 16);
            }
            #pragma unroll
            for (int mi = 0; mi < 2; mi++)
                #pragma unroll
                for (int ni = 0; ni < 4; ni++) {
                    mma_bf16(acc[mi][ni], a[mi], bh[ni]);   // Ah*Bh
                    mma_bf16(acc[mi][ni], a[mi], bl[ni]);   // Ah*Bl
                }
            #pragma unroll
            for (int mi = 0; mi < 2; mi++) {
                const char* ab = sAlo + (warp_m * 32 + mi * 16 + frow) * ROWB + koff;
                a[mi][0] = *(const uint32_t*)(ab);
                a[mi][1] = *(const uint32_t*)(ab + 8 * ROWB);
                a[mi][2] = *(const uint32_t*)(ab + 16);
                a[mi][3] = *(const uint32_t*)(ab + 8 * ROWB + 16);
            }
            #pragma unroll
            for (int mi = 0; mi < 2; mi++)
                #pragma unroll
                for (int ni = 0; ni < 4; ni++)
                    mma_bf16(acc[mi][ni], a[mi], bh[ni]);   // Al*Bh
        }

        // ---- epilogue ----
        #pragma unroll
        for (int mi = 0; mi < 2; mi++) {
            const int r0 = m0 + warp_m * 32 + mi * 16 + frow;
            float* crow0 = C + (long long)r0 * ldc;
            float* crow1 = C + (long long)(r0 + 8) * ldc;
            #pragma unroll
            for (int ni = 0; ni < 4; ni++) {
                const int nl = warp_n * 32 + ni * 8 + (lane & 3) * 2;
                const int n  = n0 + nl;
                const float b0 = sbias[nl], b1 = sbias[nl + 1];
                if (n < nvalid) {
                    crow0[n] = acc[mi][ni][0] + b0;
                    crow1[n] = acc[mi][ni][2] + b0;
                }
                if (n + 1 < nvalid) {
                    crow0[n + 1] = acc[mi][ni][1] + b1;
                    crow1[n + 1] = acc[mi][ni][3] + b1;
                }
            }
        }
    }
}

// =====================================================================
// K6: attention, one block per (b,h); emits bf16 hi/lo directly
// =====================================================================
__global__ __launch_bounds__(256)
void attn_kernel(const float* __restrict__ qkv, const int* __restrict__ seq,
                 __nv_bfloat16* __restrict__ avhi, __nv_bfloat16* __restrict__ avlo)
{
    __shared__ float sq[SS][33], sk[SS][33], sv[SS][33];
    __shared__ float sc[SS][52];
    __shared__ int   spad[SS];

    int b = blockIdx.x >> 2;
    int h = blockIdx.x & 3;
    int tid = threadIdx.x;

    for (int idx = tid; idx < SS * 32; idx += 256) {
        int s = idx >> 5, i = idx & 31;
        size_t base = ((size_t)(b * SS + s)) * 384 + h * 32 + i;
        sq[s][i] = qkv[base];
        sk[s][i] = qkv[base + 128];
        sv[s][i] = qkv[base + 256];
    }
    if (tid < SS) spad[tid] = (seq[b * SS + tid] == 0);
    __syncthreads();

    for (int idx = tid; idx < SS * SS; idx += 256) {
        int qi = idx / SS;
        int kj = idx - qi * SS;
        float acc = 0.f;
        #pragma unroll
        for (int i = 0; i < 32; i++) acc += sq[qi][i] * sk[kj][i];
        acc *= (1.0f / 32.0f);
        if (spad[qi] | spad[kj]) acc = NEGV;
        sc[qi][kj] = acc;
    }
    __syncthreads();

    int wid = tid >> 5, lane = tid & 31;
    for (int r = wid; r < SS; r += 8) {
        float m = -INFINITY;
        for (int j = lane; j < SS; j += 32) m = fmaxf(m, sc[r][j]);
        #pragma unroll
        for (int o = 16; o; o >>= 1) m = fmaxf(m, __shfl_xor_sync(0xffffffffu, m, o));
        float sum = 0.f;
        for (int j = lane; j < SS; j += 32) {
            float e = expf(sc[r][j] - m);
            sc[r][j] = e;
            sum += e;
        }
        #pragma unroll
        for (int o = 16; o; o >>= 1) sum += __shfl_xor_sync(0xffffffffu, sum, o);
        float inv = 1.0f / sum;
        for (int j = lane; j < SS; j += 32) sc[r][j] *= inv;
    }
    __syncthreads();

    for (int idx = tid; idx < SS * 32; idx += 256) {
        int s = idx >> 5, i = idx & 31;
        float acc = 0.f;
        #pragma unroll
        for (int j = 0; j < SS; j++) acc += sc[s][j] * sv[j][i];
        size_t o = ((size_t)(b * SS + s)) * DD + h * 32 + i;
        __nv_bfloat16 hh = __float2bfloat16(acc);
        avhi[o] = hh;
        avlo[o] = __float2bfloat16(acc - __bfloat162float(hh));
    }
}

// =====================================================================
// K7: SelfEnc pooling, one block per batch; emits bf16 hi/lo directly
// =====================================================================
__global__ __launch_bounds__(128)
void pool_kernel(const float* __restrict__ enc, const float* __restrict__ w_enc,
                 const float* __restrict__ b_enc,
                 __nv_bfloat16* __restrict__ phi, __nv_bfloat16* __restrict__ plo)
{
    __shared__ float se[SS][DD];
    __shared__ float swt[SS];
    __shared__ float swe[DD];
    int b = blockIdx.x;
    int tid = threadIdx.x;

    swe[tid] = w_enc[tid];
    for (int idx = tid; idx < SS * DD; idx += 128)
        se[idx >> 7][idx & 127] = enc[(size_t)b * SS * DD + idx];
    __syncthreads();

    int wid = tid >> 5, lane = tid & 31;
    for (int s = wid; s < SS; s += 4) {
        float acc = 0.f;
        #pragma unroll
        for (int d = lane; d < DD; d += 32) acc += se[s][d] * swe[d];
        #pragma unroll
        for (int o = 16; o; o >>= 1) acc += __shfl_xor_sync(0xffffffffu, acc, o);
        if (lane == 0) swt[s] = acc + b_enc[0];
    }
    __syncthreads();

    float acc = 0.f;
    #pragma unroll
    for (int s = 0; s < SS; s++) acc += swt[s] * se[s][tid];
    __nv_bfloat16 h = __float2bfloat16(acc);
    phi[b * DD + tid] = h;
    plo[b * DD + tid] = __float2bfloat16(acc - __bfloat162float(h));
}

// =====================================================================
// K8: consumed-item mask scatter
// =====================================================================
__global__ void mask_kernel(const int* __restrict__ seq, float* __restrict__ out)
{
    int b = blockIdx.x;
    int s = threadIdx.x;
    if (s < SS) out[(size_t)b * VV + seq[b * SS + s]] = NEGV;
}

// =====================================================================
// launch
// =====================================================================
extern "C" void kernel_launch(void* const* d_in, const int* in_sizes, int n_in,
                              void* d_out, int out_size)
{
    const int*   seq    = (const int*)  d_in[0];
    const int*   subty  = (const int*)  d_in[1];
    const float* emb    = (const float*)d_in[2];
    const float* sgt    = (const float*)d_in[3];
    const float* wq     = (const float*)d_in[4];
    const float* bq     = (const float*)d_in[5];
    const float* wk     = (const float*)d_in[6];
    const float* bk     = (const float*)d_in[7];
    const float* wv     = (const float*)d_in[8];
    const float* bv     = (const float*)d_in[9];
    const float* wo     = (const float*)d_in[10];
    const float* bo     = (const float*)d_in[11];
    const float* w_enc  = (const float*)d_in[12];
    const float* b_enc  = (const float*)d_in[13];
    const float* wscore = (const float*)d_in[14];
    const float* bscore = (const float*)d_in[15];
    float* out = (float*)d_out;

    __nv_bfloat16 *xhi, *xlo, *avhi, *avlo, *phi, *plo, *wshi, *wslo, *w4hi, *w4lo;
    float *qkv, *enc, *b3;
    cudaGetSymbolAddress((void**)&xhi,  g_xhi);
    cudaGetSymbolAddress((void**)&xlo,  g_xlo);
    cudaGetSymbolAddress((void**)&qkv,  g_qkv);
    cudaGetSymbolAddress((void**)&avhi, g_avhi);
    cudaGetSymbolAddress((void**)&avlo, g_avlo);
    cudaGetSymbolAddress((void**)&enc,  g_enc);
    cudaGetSymbolAddress((void**)&phi,  g_phi);
    cudaGetSymbolAddress((void**)&plo,  g_plo);
    cudaGetSymbolAddress((void**)&wshi, g_wshi);
    cudaGetSymbolAddress((void**)&wslo, g_wslo);
    cudaGetSymbolAddress((void**)&w4hi, g_w4hi);
    cudaGetSymbolAddress((void**)&w4lo, g_w4lo);
    cudaGetSymbolAddress((void**)&b3,   g_b3);

    const int GEMM_SMEM = 2 * TILE_B_SMEM + 2 * TILE_A_SMEM + 512;   // 104960
    cudaFuncSetAttribute(mma_gemm, cudaFuncAttributeMaxDynamicSharedMemorySize, GEMM_SMEM);

    // 1) embed + PE -> bf16 hi/lo
    embed_kernel<<<BS, 128>>>(seq, subty, emb, sgt, xhi, xlo);

    // 2) weight transpose + split (fused 4x small, then w_score)
    wsplit4_kernel<<<dim3(4, 4), 128>>>(wq, wk, wv, wo, w4hi, w4lo);
    wsplitV_kernel<<<VV_PAD / 32, 128>>>(wscore, wshi, wslo);

    // 3) bias concat
    bias3_kernel<<<1, 384>>>(bq, bk, bv, b3);

    // 4) fused QKV projection: B = [wq^T|wk^T|wv^T] (384 rows), C ldc=384
    mma_gemm<<<dim3(3, BS / 64), 256, GEMM_SMEM>>>(xhi, xlo, w4hi, w4lo,
                                                   b3, qkv, 384, 384, 1);

    // 5) attention (emits avhi/avlo)
    attn_kernel<<<BB * HH, 256>>>(qkv, seq, avhi, avlo);

    // 6) output projection
    mma_gemm<<<dim3(1, BS / 64), 256, GEMM_SMEM>>>(avhi, avlo,
                                                   w4hi + 3 * DD * DD, w4lo + 3 * DD * DD,
                                                   bo, enc, DD, DD, 1);

    // 7) pooling (emits phi/plo)
    pool_kernel<<<BB, 128>>>(enc, w_enc, b_enc, phi, plo);

    // 8) novelty scores: grid (782 n-tiles, 4 m-groups), 4 M-tiles each
    mma_gemm<<<dim3(VV_PAD / 128, 4), 256, GEMM_SMEM>>>(phi, plo, wshi, wslo,
                                                        bscore, out,
                                                        (long long)VV, VV, 4);

    // 9) consumed mask
    mask_kernel<<<BB, 64>>>(seq, out);
}

// round 5
// speedup vs baseline: 2.9698x; 1.3030x over previous
#include <cuda_runtime.h>
#include <cuda_bf16.h>
#include <math.h>
#include <stdint.h>

// Problem constants
#define BB   1024
#define SS   49
#define DD   128
#define HH   4
#define VV   100001
#define VV_PAD 100096            // 782 * 128
#define BS   (BB*SS)             // 50176
#define NEGV (-1e8f)

// =====================================================================
// scratch (device globals: no allocs allowed)
// =====================================================================
__device__ __align__(256) __nv_bfloat16 g_x   [BS * DD];              // embedded, bf16
__device__ __align__(256) float         g_qkv [BS * 3 * DD];          // q|k|v concat, ld=384
__device__ __align__(256) __nv_bfloat16 g_av  [BS * DD];              // attention out, bf16
__device__ __align__(256) float         g_enc [BS * DD];
__device__ __align__(256) __nv_bfloat16 g_p   [BB * DD];              // pooled, bf16
__device__ __align__(256) __nv_bfloat16 g_ws  [(size_t)VV_PAD * DD];  // w_score^T [n][k] bf16
__device__ __align__(256) __nv_bfloat16 g_w4  [4][DD * DD];           // wq,wk,wv,wo ^T bf16
__device__ __align__(256) float         g_b3  [3 * DD];               // bq|bk|bv concat

// =====================================================================
// warp MMA: m16n8k16 bf16 -> fp32 accumulate
// =====================================================================
__device__ __forceinline__ void mma_bf16(float* c, const uint32_t* a, const uint32_t* b) {
    asm volatile(
        "mma.sync.aligned.m16n8k16.row.col.f32.bf16.bf16.f32 "
        "{%0,%1,%2,%3}, {%4,%5,%6,%7}, {%8,%9}, {%0,%1,%2,%3};"
        : "+f"(c[0]), "+f"(c[1]), "+f"(c[2]), "+f"(c[3])
        : "r"(a[0]), "r"(a[1]), "r"(a[2]), "r"(a[3]), "r"(b[0]), "r"(b[1]));
}

// smem tile geometry: rows x 128 bf16, padded row stride = 272 bytes
// (272 = 68 words; 68*r mod 32 = 4r mod 32 -> 8 fragment rows hit 8 distinct
//  bank groups -> conflict-free 32-bit fragment loads)
#define ROWB 272
#define TILE_B_SMEM (128 * ROWB)   // 34816
#define TILE_A_SMEM (64  * ROWB)   // 17408

// =====================================================================
// K1: embedding + subgenre + positional encoding -> bf16
// =====================================================================
__global__ void embed_kernel(const int* __restrict__ seq, const int* __restrict__ sub,
                             const float* __restrict__ emb, const float* __restrict__ sgt,
                             __nv_bfloat16* __restrict__ x)
{
    int bs = blockIdx.x;
    int d  = threadIdx.x;
    int s  = bs % SS;
    int item = seq[bs];
    int st   = sub[bs];
    float pe = (d & 1) ? cosf((float)s) : sinf((float)s);
    float v  = emb[(size_t)item * DD + d] + sgt[(size_t)st * DD + d] + pe;
    x[(size_t)bs * DD + d] = __float2bfloat16(v);
}

// =====================================================================
// K2: fused transpose for the four 128x128 weights -> bf16
// grid = (4 n-blocks, 4 weights)
// =====================================================================
__global__ __launch_bounds__(128)
void wsplit4_kernel(const float* __restrict__ w0, const float* __restrict__ w1,
                    const float* __restrict__ w2, const float* __restrict__ w3,
                    __nv_bfloat16* __restrict__ T4)
{
    __shared__ float st[32][129];
    int t = threadIdx.x;
    int n0 = blockIdx.x * 32;
    int w  = blockIdx.y;
    const float* W = (w == 0) ? w0 : (w == 1) ? w1 : (w == 2) ? w2 : w3;
    __nv_bfloat16* T = T4 + (size_t)w * DD * DD;
    #pragma unroll
    for (int rep = 0; rep < 32; rep++) {
        int i = rep * 128 + t;
        int k = i >> 5, j = i & 31;
        st[j][k] = W[(size_t)k * DD + n0 + j];
    }
    __syncthreads();
    #pragma unroll
    for (int rep = 0; rep < 32; rep++) {
        int i = rep * 128 + t;
        int nl = i >> 7, k = i & 127;
        T[(size_t)(n0 + nl) * DD + k] = __float2bfloat16(st[nl][k]);
    }
}

// =====================================================================
// K3: transpose w_score: W[k=128][VV] -> T[VV_PAD][128] bf16
// =====================================================================
__global__ __launch_bounds__(128)
void wsplitV_kernel(const float* __restrict__ W, __nv_bfloat16* __restrict__ T)
{
    __shared__ float st[32][129];
    int t = threadIdx.x;
    int n0 = blockIdx.x * 32;
    #pragma unroll
    for (int rep = 0; rep < 32; rep++) {
        int i = rep * 128 + t;
        int k = i >> 5, j = i & 31;
        int n = n0 + j;
        st[j][k] = (n < VV) ? W[(size_t)k * VV + n] : 0.f;
    }
    __syncthreads();
    #pragma unroll
    for (int rep = 0; rep < 32; rep++) {
        int i = rep * 128 + t;
        int nl = i >> 7, k = i & 127;
        T[(size_t)(n0 + nl) * DD + k] = __float2bfloat16(st[nl][k]);
    }
}

// =====================================================================
// K4: bias concat bq|bk|bv
// =====================================================================
__global__ void bias3_kernel(const float* __restrict__ bq, const float* __restrict__ bk,
                             const float* __restrict__ bv, float* __restrict__ b3)
{
    int t = threadIdx.x;   // 384
    b3[t] = (t < 128) ? bq[t] : (t < 256) ? bk[t - 128] : bv[t - 256];
}

// =====================================================================
// K5: bf16 tensor-core GEMM via mma.sync  (M-tile 64, N-tile 128)
// C[m,n] = A[m,k=128] @ B[n,k=128]^T + bias[n]
// grid=(nTiles, mGroups); each CTA loops m_iters M-tiles with B resident.
// smem ~52KB -> 3+ CTAs/SM.
// =====================================================================
__device__ __forceinline__ void load_tile_128(char* s, const __nv_bfloat16* g, int t)
{
    #pragma unroll
    for (int i = 0; i < 8; i++) {
        int idx = i * 256 + t;          // 2048 uint4
        int r = idx >> 4, seg = idx & 15;
        uint4 v = *reinterpret_cast<const uint4*>(g + (size_t)r * DD + seg * 8);
        *reinterpret_cast<uint4*>(s + r * ROWB + seg * 16) = v;
    }
}
__device__ __forceinline__ void load_tile_64(char* s, const __nv_bfloat16* g, int t)
{
    #pragma unroll
    for (int i = 0; i < 4; i++) {
        int idx = i * 256 + t;          // 1024 uint4
        int r = idx >> 4, seg = idx & 15;
        uint4 v = *reinterpret_cast<const uint4*>(g + (size_t)r * DD + seg * 8);
        *reinterpret_cast<uint4*>(s + r * ROWB + seg * 16) = v;
    }
}

__global__ __launch_bounds__(256, 3)
void mma_gemm(const __nv_bfloat16* __restrict__ A, const __nv_bfloat16* __restrict__ B,
              const float* __restrict__ bias, float* __restrict__ C,
              long long ldc, int nvalid, int m_iters)
{
    extern __shared__ char sm[];
    char* sB = sm;
    char* sA = sB + TILE_B_SMEM;
    float* sbias = (float*)(sA + TILE_A_SMEM);

    const int t = threadIdx.x;
    const int lane = t & 31;
    const int wid  = t >> 5;
    const int warp_m = wid >> 2;        // 0..1  (32 rows each)
    const int warp_n = wid & 3;         // 0..3  (32 cols each)
    const int n0 = blockIdx.x * 128;

    // ---- B tile + bias: loaded once, reused across all M iterations ----
    load_tile_128(sB, B + (size_t)n0 * DD, t);
    if (t < 128) {
        int n = n0 + t;
        sbias[t] = (n < nvalid) ? bias[n] : 0.f;
    }

    const int frow = lane >> 2;         // 0..7
    const int fcol = (lane & 3) * 4;    // byte offset of 2-bf16 pair

    for (int iter = 0; iter < m_iters; iter++) {
        const int m0 = (blockIdx.y * m_iters + iter) * 64;
        __syncthreads();                // previous compute done before overwrite
        load_tile_64(sA, A + (size_t)m0 * DD, t);
        __syncthreads();

        float acc[2][4][4];
        #pragma unroll
        for (int mi = 0; mi < 2; mi++)
            #pragma unroll
            for (int ni = 0; ni < 4; ni++)
                #pragma unroll
                for (int e = 0; e < 4; e++) acc[mi][ni][e] = 0.f;

        #pragma unroll
        for (int kb = 0; kb < 8; kb++) {
            const int koff = kb * 32 + fcol;

            uint32_t bf[4][2];
            #pragma unroll
            for (int ni = 0; ni < 4; ni++) {
                const char* bb = sB + (warp_n * 32 + ni * 8 + frow) * ROWB + koff;
                bf[ni][0] = *(const uint32_t*)(bb);
                bf[ni][1] = *(const uint32_t*)(bb + 16);
            }
            uint32_t a[2][4];
            #pragma unroll
            for (int mi = 0; mi < 2; mi++) {
                const char* ab = sA + (warp_m * 32 + mi * 16 + frow) * ROWB + koff;
                a[mi][0] = *(const uint32_t*)(ab);
                a[mi][1] = *(const uint32_t*)(ab + 8 * ROWB);
                a[mi][2] = *(const uint32_t*)(ab + 16);
                a[mi][3] = *(const uint32_t*)(ab + 8 * ROWB + 16);
            }
            #pragma unroll
            for (int mi = 0; mi < 2; mi++)
                #pragma unroll
                for (int ni = 0; ni < 4; ni++)
                    mma_bf16(acc[mi][ni], a[mi], bf[ni]);
        }

        // ---- epilogue ----
        #pragma unroll
        for (int mi = 0; mi < 2; mi++) {
            const int r0 = m0 + warp_m * 32 + mi * 16 + frow;
            float* crow0 = C + (long long)r0 * ldc;
            float* crow1 = C + (long long)(r0 + 8) * ldc;
            #pragma unroll
            for (int ni = 0; ni < 4; ni++) {
                const int nl = warp_n * 32 + ni * 8 + (lane & 3) * 2;
                const int n  = n0 + nl;
                const float b0 = sbias[nl], b1 = sbias[nl + 1];
                if (n < nvalid) {
                    crow0[n] = acc[mi][ni][0] + b0;
                    crow1[n] = acc[mi][ni][2] + b0;
                }
                if (n + 1 < nvalid) {
                    crow0[n + 1] = acc[mi][ni][1] + b1;
                    crow1[n + 1] = acc[mi][ni][3] + b1;
                }
            }
        }
    }
}

// =====================================================================
// K6: attention, one block per (b,h); emits bf16
// =====================================================================
__global__ __launch_bounds__(256)
void attn_kernel(const float* __restrict__ qkv, const int* __restrict__ seq,
                 __nv_bfloat16* __restrict__ av)
{
    __shared__ float sq[SS][33], sk[SS][33], sv[SS][33];
    __shared__ float sc[SS][52];
    __shared__ int   spad[SS];

    int b = blockIdx.x >> 2;
    int h = blockIdx.x & 3;
    int tid = threadIdx.x;

    for (int idx = tid; idx < SS * 32; idx += 256) {
        int s = idx >> 5, i = idx & 31;
        size_t base = ((size_t)(b * SS + s)) * 384 + h * 32 + i;
        sq[s][i] = qkv[base];
        sk[s][i] = qkv[base + 128];
        sv[s][i] = qkv[base + 256];
    }
    if (tid < SS) spad[tid] = (seq[b * SS + tid] == 0);
    __syncthreads();

    for (int idx = tid; idx < SS * SS; idx += 256) {
        int qi = idx / SS;
        int kj = idx - qi * SS;
        float acc = 0.f;
        #pragma unroll
        for (int i = 0; i < 32; i++) acc += sq[qi][i] * sk[kj][i];
        acc *= (1.0f / 32.0f);
        if (spad[qi] | spad[kj]) acc = NEGV;
        sc[qi][kj] = acc;
    }
    __syncthreads();

    int wid = tid >> 5, lane = tid & 31;
    for (int r = wid; r < SS; r += 8) {
        float m = -INFINITY;
        for (int j = lane; j < SS; j += 32) m = fmaxf(m, sc[r][j]);
        #pragma unroll
        for (int o = 16; o; o >>= 1) m = fmaxf(m, __shfl_xor_sync(0xffffffffu, m, o));
        float sum = 0.f;
        for (int j = lane; j < SS; j += 32) {
            float e = expf(sc[r][j] - m);
            sc[r][j] = e;
            sum += e;
        }
        #pragma unroll
        for (int o = 16; o; o >>= 1) sum += __shfl_xor_sync(0xffffffffu, sum, o);
        float inv = 1.0f / sum;
        for (int j = lane; j < SS; j += 32) sc[r][j] *= inv;
    }
    __syncthreads();

    for (int idx = tid; idx < SS * 32; idx += 256) {
        int s = idx >> 5, i = idx & 31;
        float acc = 0.f;
        #pragma unroll
        for (int j = 0; j < SS; j++) acc += sc[s][j] * sv[j][i];
        av[((size_t)(b * SS + s)) * DD + h * 32 + i] = __float2bfloat16(acc);
    }
}

// =====================================================================
// K7: SelfEnc pooling, one block per batch; emits bf16
// =====================================================================
__global__ __launch_bounds__(128)
void pool_kernel(const float* __restrict__ enc, const float* __restrict__ w_enc,
                 const float* __restrict__ b_enc, __nv_bfloat16* __restrict__ p)
{
    __shared__ float se[SS][DD];
    __shared__ float swt[SS];
    __shared__ float swe[DD];
    int b = blockIdx.x;
    int tid = threadIdx.x;

    swe[tid] = w_enc[tid];
    for (int idx = tid; idx < SS * DD; idx += 128)
        se[idx >> 7][idx & 127] = enc[(size_t)b * SS * DD + idx];
    __syncthreads();

    int wid = tid >> 5, lane = tid & 31;
    for (int s = wid; s < SS; s += 4) {
        float acc = 0.f;
        #pragma unroll
        for (int d = lane; d < DD; d += 32) acc += se[s][d] * swe[d];
        #pragma unroll
        for (int o = 16; o; o >>= 1) acc += __shfl_xor_sync(0xffffffffu, acc, o);
        if (lane == 0) swt[s] = acc + b_enc[0];
    }
    __syncthreads();

    float acc = 0.f;
    #pragma unroll
    for (int s = 0; s < SS; s++) acc += swt[s] * se[s][tid];
    p[b * DD + tid] = __float2bfloat16(acc);
}

// =====================================================================
// K8: consumed-item mask scatter
// =====================================================================
__global__ void mask_kernel(const int* __restrict__ seq, float* __restrict__ out)
{
    int b = blockIdx.x;
    int s = threadIdx.x;
    if (s < SS) out[(size_t)b * VV + seq[b * SS + s]] = NEGV;
}

// =====================================================================
// launch
// =====================================================================
extern "C" void kernel_launch(void* const* d_in, const int* in_sizes, int n_in,
                              void* d_out, int out_size)
{
    const int*   seq    = (const int*)  d_in[0];
    const int*   subty  = (const int*)  d_in[1];
    const float* emb    = (const float*)d_in[2];
    const float* sgt    = (const float*)d_in[3];
    const float* wq     = (const float*)d_in[4];
    const float* bq     = (const float*)d_in[5];
    const float* wk     = (const float*)d_in[6];
    const float* bk     = (const float*)d_in[7];
    const float* wv     = (const float*)d_in[8];
    const float* bv     = (const float*)d_in[9];
    const float* wo     = (const float*)d_in[10];
    const float* bo     = (const float*)d_in[11];
    const float* w_enc  = (const float*)d_in[12];
    const float* b_enc  = (const float*)d_in[13];
    const float* wscore = (const float*)d_in[14];
    const float* bscore = (const float*)d_in[15];
    float* out = (float*)d_out;

    __nv_bfloat16 *x, *av, *p, *ws, *w4;
    float *qkv, *enc, *b3;
    cudaGetSymbolAddress((void**)&x,    g_x);
    cudaGetSymbolAddress((void**)&qkv,  g_qkv);
    cudaGetSymbolAddress((void**)&av,   g_av);
    cudaGetSymbolAddress((void**)&enc,  g_enc);
    cudaGetSymbolAddress((void**)&p,    g_p);
    cudaGetSymbolAddress((void**)&ws,   g_ws);
    cudaGetSymbolAddress((void**)&w4,   g_w4);
    cudaGetSymbolAddress((void**)&b3,   g_b3);

    const int GEMM_SMEM = TILE_B_SMEM + TILE_A_SMEM + 512;   // 52736
    cudaFuncSetAttribute(mma_gemm, cudaFuncAttributeMaxDynamicSharedMemorySize, GEMM_SMEM);

    // 1) embed + PE -> bf16
    embed_kernel<<<BS, 128>>>(seq, subty, emb, sgt, x);

    // 2) weight transpose -> bf16
    wsplit4_kernel<<<dim3(4, 4), 128>>>(wq, wk, wv, wo, w4);
    wsplitV_kernel<<<VV_PAD / 32, 128>>>(wscore, ws);

    // 3) bias concat
    bias3_kernel<<<1, 384>>>(bq, bk, bv, b3);

    // 4) fused QKV projection: B = [wq^T|wk^T|wv^T] (384 rows), C ldc=384
    mma_gemm<<<dim3(3, BS / 64), 256, GEMM_SMEM>>>(x, w4, b3, qkv, 384, 384, 1);

    // 5) attention (emits bf16 av)
    attn_kernel<<<BB * HH, 256>>>(qkv, seq, av);

    // 6) output projection
    mma_gemm<<<dim3(1, BS / 64), 256, GEMM_SMEM>>>(av, w4 + 3 * DD * DD,
                                                   bo, enc, DD, DD, 1);

    // 7) pooling (emits bf16 p)
    pool_kernel<<<BB, 128>>>(enc, w_enc, b_enc, p);

    // 8) novelty scores: grid (782 n-tiles, 4 m-groups), 4 M-tiles each
    mma_gemm<<<dim3(VV_PAD / 128, 4), 256, GEMM_SMEM>>>(p, ws, bscore, out,
                                                        (long long)VV, VV, 4);

    // 9) consumed mask
    mask_kernel<<<BB, 64>>>(seq, out);
}

// round 7
// speedup vs baseline: 3.2731x; 1.1021x over previous
#include <cuda_runtime.h>
#include <cuda_bf16.h>
#include <math.h>
#include <stdint.h>

// Problem constants
#define BB   1024
#define SS   49
#define DD   128
#define HH   4
#define VV   100001
#define VV_PAD 100096            // 782 * 128
#define BS   (BB*SS)             // 50176
#define NEGV (-1e8f)

// =====================================================================
// scratch (device globals: no allocs allowed)
// =====================================================================
__device__ __align__(256) __nv_bfloat16 g_x   [BS * DD];              // embedded, bf16
__device__ __align__(256) float         g_qkv [BS * 3 * DD];          // q|k|v concat, ld=384
__device__ __align__(256) __nv_bfloat16 g_av  [BS * DD];              // attention out, bf16
__device__ __align__(256) float         g_enc [BS * DD];
__device__ __align__(256) __nv_bfloat16 g_p   [BB * DD];              // pooled, bf16
__device__ __align__(256) __nv_bfloat16 g_ws  [(size_t)VV_PAD * DD];  // w_score^T [n][k] bf16
__device__ __align__(256) __nv_bfloat16 g_w4  [4][DD * DD];           // wq,wk,wv,wo ^T bf16
__device__ __align__(256) float         g_b3  [3 * DD];               // bq|bk|bv concat

// =====================================================================
// warp MMA: m16n8k16 bf16 -> fp32 accumulate
// =====================================================================
__device__ __forceinline__ void mma_bf16(float* c, const uint32_t* a, const uint32_t* b) {
    asm volatile(
        "mma.sync.aligned.m16n8k16.row.col.f32.bf16.bf16.f32 "
        "{%0,%1,%2,%3}, {%4,%5,%6,%7}, {%8,%9}, {%0,%1,%2,%3};"
        : "+f"(c[0]), "+f"(c[1]), "+f"(c[2]), "+f"(c[3])
        : "r"(a[0]), "r"(a[1]), "r"(a[2]), "r"(a[3]), "r"(b[0]), "r"(b[1]));
}

// smem tile geometry: rows x 128 bf16, padded row stride = 272 bytes
#define ROWB 272
#define TILE_B_SMEM (128 * ROWB)   // 34816
#define TILE_A_SMEM (64  * ROWB)   // 17408

// =====================================================================
// K1 (merged prep): embed+PE | w_score transpose | w4 transpose | bias3
// =====================================================================
#define PREP_EMBED  BS                     // 50176
#define PREP_WSV    (VV_PAD / 32)          // 3128
__global__ __launch_bounds__(128)
void prep_kernel(const int* __restrict__ seq, const int* __restrict__ sub,
                 const float* __restrict__ emb, const float* __restrict__ sgt,
                 const float* __restrict__ wscore,
                 const float* __restrict__ w0, const float* __restrict__ w1,
                 const float* __restrict__ w2, const float* __restrict__ w3,
                 const float* __restrict__ bq, const float* __restrict__ bk,
                 const float* __restrict__ bv,
                 __nv_bfloat16* __restrict__ x, __nv_bfloat16* __restrict__ ws,
                 __nv_bfloat16* __restrict__ w4, float* __restrict__ b3)
{
    __shared__ float st[32][129];
    const int bid = blockIdx.x;
    const int t = threadIdx.x;

    if (bid < PREP_EMBED) {
        int bs = bid;
        int s  = bs % SS;
        int item = seq[bs];
        int stype = sub[bs];
        float pe = (t & 1) ? cosf((float)s) : sinf((float)s);
        float v  = emb[(size_t)item * DD + t] + sgt[(size_t)stype * DD + t] + pe;
        x[(size_t)bs * DD + t] = __float2bfloat16(v);
        return;
    }
    if (bid < PREP_EMBED + PREP_WSV) {
        int n0 = (bid - PREP_EMBED) * 32;
        #pragma unroll
        for (int rep = 0; rep < 32; rep++) {
            int i = rep * 128 + t;
            int k = i >> 5, j = i & 31;
            int n = n0 + j;
            st[j][k] = (n < VV) ? wscore[(size_t)k * VV + n] : 0.f;
        }
        __syncthreads();
        #pragma unroll
        for (int rep = 0; rep < 32; rep++) {
            int i = rep * 128 + t;
            int nl = i >> 7, k = i & 127;
            ws[(size_t)(n0 + nl) * DD + k] = __float2bfloat16(st[nl][k]);
        }
        return;
    }
    if (bid < PREP_EMBED + PREP_WSV + 16) {
        int r  = bid - PREP_EMBED - PREP_WSV;
        int w  = r >> 2;
        int n0 = (r & 3) * 32;
        const float* W = (w == 0) ? w0 : (w == 1) ? w1 : (w == 2) ? w2 : w3;
        __nv_bfloat16* T = w4 + (size_t)w * DD * DD;
        #pragma unroll
        for (int rep = 0; rep < 32; rep++) {
            int i = rep * 128 + t;
            int k = i >> 5, j = i & 31;
            st[j][k] = W[(size_t)k * DD + n0 + j];
        }
        __syncthreads();
        #pragma unroll
        for (int rep = 0; rep < 32; rep++) {
            int i = rep * 128 + t;
            int nl = i >> 7, k = i & 127;
            T[(size_t)(n0 + nl) * DD + k] = __float2bfloat16(st[nl][k]);
        }
        return;
    }
    for (int i = t; i < 384; i += 128)
        b3[i] = (i < 128) ? bq[i] : (i < 256) ? bk[i - 128] : bv[i - 256];
}

// =====================================================================
// K2: bf16 tensor-core GEMM via mma.sync (M-tile 64, N-tile 128)
// Double-buffered A across m_iters; B resident.
// =====================================================================
__device__ __forceinline__ void load_tile_128(char* s, const __nv_bfloat16* g, int t)
{
    #pragma unroll
    for (int i = 0; i < 8; i++) {
        int idx = i * 256 + t;
        int r = idx >> 4, seg = idx & 15;
        uint4 v = *reinterpret_cast<const uint4*>(g + (size_t)r * DD + seg * 8);
        *reinterpret_cast<uint4*>(s + r * ROWB + seg * 16) = v;
    }
}
__device__ __forceinline__ void load_tile_64(char* s, const __nv_bfloat16* g, int t)
{
    #pragma unroll
    for (int i = 0; i < 4; i++) {
        int idx = i * 256 + t;
        int r = idx >> 4, seg = idx & 15;
        uint4 v = *reinterpret_cast<const uint4*>(g + (size_t)r * DD + seg * 8);
        *reinterpret_cast<uint4*>(s + r * ROWB + seg * 16) = v;
    }
}

__global__ __launch_bounds__(256, 3)
void mma_gemm(const __nv_bfloat16* __restrict__ A, const __nv_bfloat16* __restrict__ B,
              const float* __restrict__ bias, float* __restrict__ C,
              long long ldc, int nvalid, int m_iters)
{
    extern __shared__ char sm[];
    char* sB    = sm;
    char* sAbuf = sB + TILE_B_SMEM;                 // 2 x TILE_A_SMEM
    float* sbias = (float*)(sAbuf + 2 * TILE_A_SMEM);

    const int t = threadIdx.x;
    const int lane = t & 31;
    const int wid  = t >> 5;
    const int warp_m = wid >> 2;        // 0..1  (32 rows each)
    const int warp_n = wid & 3;         // 0..3  (32 cols each)
    const int n0 = blockIdx.x * 128;

    load_tile_128(sB, B + (size_t)n0 * DD, t);
    if (t < 128) {
        int n = n0 + t;
        sbias[t] = (n < nvalid) ? bias[n] : 0.f;
    }
    load_tile_64(sAbuf, A + (size_t)(blockIdx.y * m_iters) * 64 * DD, t);
    __syncthreads();

    const int frow = lane >> 2;
    const int fcol = (lane & 3) * 4;
    // vectorized stores need 8B-aligned row bases -> ldc must be even
    const bool fullN = (n0 + 128 <= nvalid) && ((ldc & 1LL) == 0LL);
    int cur = 0;

    for (int iter = 0; iter < m_iters; iter++) {
        const int m0 = (blockIdx.y * m_iters + iter) * 64;
        const bool has_next = (iter + 1 < m_iters);

        // prefetch next A tile into registers (overlaps with MMA compute)
        uint4 pre[4];
        if (has_next) {
            const __nv_bfloat16* gn = A + (size_t)(m0 + 64) * DD;
            #pragma unroll
            for (int i = 0; i < 4; i++) {
                int idx = i * 256 + t;
                int r = idx >> 4, seg = idx & 15;
                pre[i] = *reinterpret_cast<const uint4*>(gn + (size_t)r * DD + seg * 8);
            }
        }

        char* sA = sAbuf + cur * TILE_A_SMEM;

        float acc[2][4][4];
        #pragma unroll
        for (int mi = 0; mi < 2; mi++)
            #pragma unroll
            for (int ni = 0; ni < 4; ni++)
                #pragma unroll
                for (int e = 0; e < 4; e++) acc[mi][ni][e] = 0.f;

        #pragma unroll
        for (int kb = 0; kb < 8; kb++) {
            const int koff = kb * 32 + fcol;

            uint32_t bf[4][2];
            #pragma unroll
            for (int ni = 0; ni < 4; ni++) {
                const char* bb = sB + (warp_n * 32 + ni * 8 + frow) * ROWB + koff;
                bf[ni][0] = *(const uint32_t*)(bb);
                bf[ni][1] = *(const uint32_t*)(bb + 16);
            }
            uint32_t a[2][4];
            #pragma unroll
            for (int mi = 0; mi < 2; mi++) {
                const char* ab = sA + (warp_m * 32 + mi * 16 + frow) * ROWB + koff;
                a[mi][0] = *(const uint32_t*)(ab);
                a[mi][1] = *(const uint32_t*)(ab + 8 * ROWB);
                a[mi][2] = *(const uint32_t*)(ab + 16);
                a[mi][3] = *(const uint32_t*)(ab + 8 * ROWB + 16);
            }
            #pragma unroll
            for (int mi = 0; mi < 2; mi++)
                #pragma unroll
                for (int ni = 0; ni < 4; ni++)
                    mma_bf16(acc[mi][ni], a[mi], bf[ni]);
        }

        if (has_next) {
            char* sAn = sAbuf + (cur ^ 1) * TILE_A_SMEM;
            #pragma unroll
            for (int i = 0; i < 4; i++) {
                int idx = i * 256 + t;
                int r = idx >> 4, seg = idx & 15;
                *reinterpret_cast<uint4*>(sAn + r * ROWB + seg * 16) = pre[i];
            }
            __syncthreads();
            cur ^= 1;
        }

        // ---- epilogue ----
        #pragma unroll
        for (int mi = 0; mi < 2; mi++) {
            const int r0 = m0 + warp_m * 32 + mi * 16 + frow;
            float* crow0 = C + (long long)r0 * ldc;
            float* crow1 = C + (long long)(r0 + 8) * ldc;
            if (fullN) {
                #pragma unroll
                for (int ni = 0; ni < 4; ni++) {
                    const int nl = warp_n * 32 + ni * 8 + (lane & 3) * 2;
                    const int n  = n0 + nl;
                    float2 s0 = make_float2(acc[mi][ni][0] + sbias[nl],
                                            acc[mi][ni][1] + sbias[nl + 1]);
                    float2 s1 = make_float2(acc[mi][ni][2] + sbias[nl],
                                            acc[mi][ni][3] + sbias[nl + 1]);
                    *reinterpret_cast<float2*>(crow0 + n) = s0;
                    *reinterpret_cast<float2*>(crow1 + n) = s1;
                }
            } else {
                #pragma unroll
                for (int ni = 0; ni < 4; ni++) {
                    const int nl = warp_n * 32 + ni * 8 + (lane & 3) * 2;
                    const int n  = n0 + nl;
                    const float b0 = sbias[nl], b1 = sbias[nl + 1];
                    if (n < nvalid) {
                        crow0[n] = acc[mi][ni][0] + b0;
                        crow1[n] = acc[mi][ni][2] + b0;
                    }
                    if (n + 1 < nvalid) {
                        crow0[n + 1] = acc[mi][ni][1] + b1;
                        crow1[n + 1] = acc[mi][ni][3] + b1;
                    }
                }
            }
        }
    }
}

// =====================================================================
// K3: attention, one block per (b,h); float4-vectorized smem
// =====================================================================
__global__ __launch_bounds__(256)
void attn_kernel(const float* __restrict__ qkv, const int* __restrict__ seq,
                 __nv_bfloat16* __restrict__ av)
{
    __shared__ float sq[SS][36], sk[SS][36], sv[SS][36];   // 144B rows, 16B aligned
    __shared__ float sc[SS][52];
    __shared__ int   spad[SS];

    int b = blockIdx.x >> 2;
    int h = blockIdx.x & 3;
    int tid = threadIdx.x;

    for (int idx = tid; idx < SS * 8; idx += 256) {
        int s = idx >> 3, c = idx & 7;
        size_t base = ((size_t)(b * SS + s)) * 384 + h * 32 + c * 4;
        float4 q4 = *reinterpret_cast<const float4*>(qkv + base);
        float4 k4 = *reinterpret_cast<const float4*>(qkv + base + 128);
        float4 v4 = *reinterpret_cast<const float4*>(qkv + base + 256);
        *reinterpret_cast<float4*>(&sq[s][c * 4]) = q4;
        *reinterpret_cast<float4*>(&sk[s][c * 4]) = k4;
        *reinterpret_cast<float4*>(&sv[s][c * 4]) = v4;
    }
    if (tid < SS) spad[tid] = (seq[b * SS + tid] == 0);
    __syncthreads();

    for (int idx = tid; idx < SS * SS; idx += 256) {
        int qi = idx / SS;
        int kj = idx - qi * SS;
        const float4* q4 = reinterpret_cast<const float4*>(&sq[qi][0]);
        const float4* k4 = reinterpret_cast<const float4*>(&sk[kj][0]);
        float acc = 0.f;
        #pragma unroll
        for (int w = 0; w < 8; w++) {
            float4 a = q4[w], c = k4[w];
            acc += a.x * c.x + a.y * c.y + a.z * c.z + a.w * c.w;
        }
        acc *= (1.0f / 32.0f);
        if (spad[qi] | spad[kj]) acc = NEGV;
        sc[qi][kj] = acc;
    }
    __syncthreads();

    int wid = tid >> 5, lane = tid & 31;
    for (int r = wid; r < SS; r += 8) {
        float m = -INFINITY;
        for (int j = lane; j < SS; j += 32) m = fmaxf(m, sc[r][j]);
        #pragma unroll
        for (int o = 16; o; o >>= 1) m = fmaxf(m, __shfl_xor_sync(0xffffffffu, m, o));
        float sum = 0.f;
        for (int j = lane; j < SS; j += 32) {
            float e = expf(sc[r][j] - m);
            sc[r][j] = e;
            sum += e;
        }
        #pragma unroll
        for (int o = 16; o; o >>= 1) sum += __shfl_xor_sync(0xffffffffu, sum, o);
        float inv = 1.0f / sum;
        for (int j = lane; j < SS; j += 32) sc[r][j] *= inv;
    }
    __syncthreads();

    for (int idx = tid; idx < SS * 8; idx += 256) {
        int s = idx >> 3, c = idx & 7;
        float4 acc = make_float4(0.f, 0.f, 0.f, 0.f);
        #pragma unroll 7
        for (int j = 0; j < SS; j++) {
            float p = sc[s][j];
            float4 v4 = *reinterpret_cast<const float4*>(&sv[j][c * 4]);
            acc.x += p * v4.x; acc.y += p * v4.y;
            acc.z += p * v4.z; acc.w += p * v4.w;
        }
        size_t o = ((size_t)(b * SS + s)) * DD + h * 32 + c * 4;
        __nv_bfloat162 p0, p1;
        p0.x = __float2bfloat16(acc.x); p0.y = __float2bfloat16(acc.y);
        p1.x = __float2bfloat16(acc.z); p1.y = __float2bfloat16(acc.w);
        *reinterpret_cast<__nv_bfloat162*>(av + o)     = p0;
        *reinterpret_cast<__nv_bfloat162*>(av + o + 2) = p1;
    }
}

// =====================================================================
// K4: SelfEnc pooling, one block per batch; emits bf16
// =====================================================================
__global__ __launch_bounds__(128)
void pool_kernel(const float* __restrict__ enc, const float* __restrict__ w_enc,
                 const float* __restrict__ b_enc, __nv_bfloat16* __restrict__ p)
{
    __shared__ float se[SS][DD];
    __shared__ float swt[SS];
    __shared__ float swe[DD];
    int b = blockIdx.x;
    int tid = threadIdx.x;

    swe[tid] = w_enc[tid];
    for (int idx = tid; idx < SS * DD; idx += 128)
        se[idx >> 7][idx & 127] = enc[(size_t)b * SS * DD + idx];
    __syncthreads();

    int wid = tid >> 5, lane = tid & 31;
    for (int s = wid; s < SS; s += 4) {
        float acc = 0.f;
        #pragma unroll
        for (int d = lane; d < DD; d += 32) acc += se[s][d] * swe[d];
        #pragma unroll
        for (int o = 16; o; o >>= 1) acc += __shfl_xor_sync(0xffffffffu, acc, o);
        if (lane == 0) swt[s] = acc + b_enc[0];
    }
    __syncthreads();

    float acc = 0.f;
    #pragma unroll
    for (int s = 0; s < SS; s++) acc += swt[s] * se[s][tid];
    p[b * DD + tid] = __float2bfloat16(acc);
}

// =====================================================================
// K5: consumed-item mask scatter
// =====================================================================
__global__ void mask_kernel(const int* __restrict__ seq, float* __restrict__ out)
{
    int b = blockIdx.x;
    int s = threadIdx.x;
    if (s < SS) out[(size_t)b * VV + seq[b * SS + s]] = NEGV;
}

// =====================================================================
// launch
// =====================================================================
extern "C" void kernel_launch(void* const* d_in, const int* in_sizes, int n_in,
                              void* d_out, int out_size)
{
    const int*   seq    = (const int*)  d_in[0];
    const int*   subty  = (const int*)  d_in[1];
    const float* emb    = (const float*)d_in[2];
    const float* sgt    = (const float*)d_in[3];
    const float* wq     = (const float*)d_in[4];
    const float* bq     = (const float*)d_in[5];
    const float* wk     = (const float*)d_in[6];
    const float* bk     = (const float*)d_in[7];
    const float* wv     = (const float*)d_in[8];
    const float* bv     = (const float*)d_in[9];
    const float* wo     = (const float*)d_in[10];
    const float* bo     = (const float*)d_in[11];
    const float* w_enc  = (const float*)d_in[12];
    const float* b_enc  = (const float*)d_in[13];
    const float* wscore = (const float*)d_in[14];
    const float* bscore = (const float*)d_in[15];
    float* out = (float*)d_out;

    __nv_bfloat16 *x, *av, *p, *ws, *w4;
    float *qkv, *enc, *b3;
    cudaGetSymbolAddress((void**)&x,    g_x);
    cudaGetSymbolAddress((void**)&qkv,  g_qkv);
    cudaGetSymbolAddress((void**)&av,   g_av);
    cudaGetSymbolAddress((void**)&enc,  g_enc);
    cudaGetSymbolAddress((void**)&p,    g_p);
    cudaGetSymbolAddress((void**)&ws,   g_ws);
    cudaGetSymbolAddress((void**)&w4,   g_w4);
    cudaGetSymbolAddress((void**)&b3,   g_b3);

    const int GEMM_SMEM = TILE_B_SMEM + 2 * TILE_A_SMEM + 512;   // 70144
    cudaFuncSetAttribute(mma_gemm, cudaFuncAttributeMaxDynamicSharedMemorySize, GEMM_SMEM);

    // 1) merged prep: embed+PE, weight transposes, bias concat
    prep_kernel<<<PREP_EMBED + PREP_WSV + 16 + 1, 128>>>(
        seq, subty, emb, sgt, wscore, wq, wk, wv, wo, bq, bk, bv,
        x, ws, w4, b3);

    // 2) fused QKV projection: B = [wq^T|wk^T|wv^T] (384 rows), C ldc=384
    mma_gemm<<<dim3(3, BS / 64), 256, GEMM_SMEM>>>(x, w4, b3, qkv, 384, 384, 1);

    // 3) attention (emits bf16 av)
    attn_kernel<<<BB * HH, 256>>>(qkv, seq, av);

    // 4) output projection
    mma_gemm<<<dim3(1, BS / 64), 256, GEMM_SMEM>>>(av, w4 + 3 * DD * DD,
                                                   bo, enc, DD, DD, 1);

    // 5) pooling (emits bf16 p)
    pool_kernel<<<BB, 128>>>(enc, w_enc, b_enc, p);

    // 6) novelty scores: grid (782 n-tiles, 4 m-groups), 4 M-tiles each
    mma_gemm<<<dim3(VV_PAD / 128, 4), 256, GEMM_SMEM>>>(p, ws, bscore, out,
                                                        (long long)VV, VV, 4);

    // 7) consumed mask
    mask_kernel<<<BB, 64>>>(seq, out);
}